// round 2
// baseline (speedup 1.0000x reference)
#include <cuda_runtime.h>
#include <math.h>

#define F      128
#define NMAX   80000
#define EMAX   640000

// ---------------- scratch (static device globals; no allocation) ----------------
__device__ float g_buf0[NMAX * F];   // GEMM out A
__device__ float g_buf1[NMAX * F];   // GEMM out B
__device__ float g_h   [NMAX * F];   // hidden after conv1+relu
__device__ float g_z   [NMAX * F];   // reparameterized latent
__device__ float g_dinv[NMAX];
__device__ int   g_deg [NMAX];
__device__ int   g_rowptr[NMAX + 1];
__device__ int   g_cur [NMAX];
__device__ int   g_csr [EMAX];       // src ids grouped by dst

// ---------------- CSR construction ----------------
__global__ void k_zero_deg(int n) {
    int i = blockIdx.x * blockDim.x + threadIdx.x;
    if (i < n) g_deg[i] = 0;
}

__global__ void k_count(const int* __restrict__ dst, int e) {
    int i = blockIdx.x * blockDim.x + threadIdx.x;
    if (i < e) atomicAdd(&g_deg[dst[i]], 1);
}

// single-block scan over node degrees; also computes dinv = rsqrt(deg+1)
__global__ void k_scan(int n) {
    __shared__ int sums[1024];
    int t = threadIdx.x;
    int chunk = (n + 1023) >> 10;
    int beg = t * chunk;
    int end = beg + chunk; if (end > n) end = n;
    if (beg > n) beg = n;

    int s = 0;
    for (int i = beg; i < end; i++) {
        int d = g_deg[i];
        g_dinv[i] = rsqrtf((float)(d + 1));   // +1 self loop; always > 0
        s += d;
    }
    sums[t] = s;
    __syncthreads();
    // inclusive scan
    for (int off = 1; off < 1024; off <<= 1) {
        int v = 0;
        if (t >= off) v = sums[t - off];
        __syncthreads();
        sums[t] += v;
        __syncthreads();
    }
    int run = sums[t] - s;   // exclusive base for this chunk
    for (int i = beg; i < end; i++) {
        g_rowptr[i] = run;
        g_cur[i]    = run;
        run += g_deg[i];
    }
    if (t == 0) g_rowptr[n] = sums[1023];
}

__global__ void k_place(const int* __restrict__ src, const int* __restrict__ dst, int e) {
    int i = blockIdx.x * blockDim.x + threadIdx.x;
    if (i < e) {
        int d = dst[i];
        int slot = atomicAdd(&g_cur[d], 1);
        g_csr[slot] = src[i];
    }
}

// ---------------- SGEMM: C[n x 128] = A[n x 128] @ B[128 x 128] ----------------
// block tile 128x128, 256 threads, 8x8 microtile per thread
__global__ __launch_bounds__(256, 2) void k_gemm(const float* __restrict__ A,
                                                 const float* __restrict__ B,
                                                 float* __restrict__ C, int n) {
    __shared__ float As[16][128];   // [k][row]
    __shared__ float Bs[16][128];   // [k][col]

    const int tid  = threadIdx.x;
    const int row0 = blockIdx.x * 128;
    const int ty   = tid >> 4;       // 0..15
    const int tx   = tid & 15;       // 0..15

    float acc[8][8];
#pragma unroll
    for (int i = 0; i < 8; i++)
#pragma unroll
        for (int j = 0; j < 8; j++) acc[i][j] = 0.0f;

    const int aRow = tid >> 1;            // 0..127
    const int aSeg = (tid & 1) << 3;      // 0 or 8
    const int bK   = tid >> 4;            // 0..15
    const int bCol = (tid & 15) << 3;     // 0..120

    int arow_g = row0 + aRow; if (arow_g >= n) arow_g = n - 1;   // clamp (safe; stores guarded)
    const float* Aptr = A + (size_t)arow_g * F + aSeg;
    const float* Bptr = B + bK * F + bCol;

    for (int kk = 0; kk < F; kk += 16) {
        float4 a0 = *(const float4*)(Aptr + kk);
        float4 a1 = *(const float4*)(Aptr + kk + 4);
        float4 b0 = *(const float4*)(Bptr + kk * F);
        float4 b1 = *(const float4*)(Bptr + kk * F + 4);

        As[aSeg + 0][aRow] = a0.x; As[aSeg + 1][aRow] = a0.y;
        As[aSeg + 2][aRow] = a0.z; As[aSeg + 3][aRow] = a0.w;
        As[aSeg + 4][aRow] = a1.x; As[aSeg + 5][aRow] = a1.y;
        As[aSeg + 6][aRow] = a1.z; As[aSeg + 7][aRow] = a1.w;
        *(float4*)&Bs[bK][bCol]     = b0;
        *(float4*)&Bs[bK][bCol + 4] = b1;
        __syncthreads();

#pragma unroll
        for (int kc = 0; kc < 16; kc++) {
            float4 ra0 = *(const float4*)&As[kc][ty * 8];
            float4 ra1 = *(const float4*)&As[kc][ty * 8 + 4];
            float4 rb0 = *(const float4*)&Bs[kc][tx * 8];
            float4 rb1 = *(const float4*)&Bs[kc][tx * 8 + 4];
            float a[8] = {ra0.x, ra0.y, ra0.z, ra0.w, ra1.x, ra1.y, ra1.z, ra1.w};
            float b[8] = {rb0.x, rb0.y, rb0.z, rb0.w, rb1.x, rb1.y, rb1.z, rb1.w};
#pragma unroll
            for (int i = 0; i < 8; i++)
#pragma unroll
                for (int j = 0; j < 8; j++) acc[i][j] = fmaf(a[i], b[j], acc[i][j]);
        }
        __syncthreads();
    }

#pragma unroll
    for (int i = 0; i < 8; i++) {
        int r = row0 + ty * 8 + i;
        if (r < n) {
            float4 o0 = make_float4(acc[i][0], acc[i][1], acc[i][2], acc[i][3]);
            float4 o1 = make_float4(acc[i][4], acc[i][5], acc[i][6], acc[i][7]);
            *(float4*)&C[(size_t)r * F + tx * 8]     = o0;
            *(float4*)&C[(size_t)r * F + tx * 8 + 4] = o1;
        }
    }
}

// ---------------- propagation: out = act( D^-1/2 (A+I) D^-1/2 t + bias ) ----------------
// one warp per destination node; lane handles 4 features (float4). Pure gather, no atomics.
__global__ __launch_bounds__(256) void k_prop(const float* __restrict__ t,
                                              const float* __restrict__ bias,
                                              float* __restrict__ out, int n, int act) {
    int w = (blockIdx.x * blockDim.x + threadIdx.x) >> 5;
    if (w >= n) return;
    int lane = threadIdx.x & 31;

    const float4* t4 = (const float4*)t;
    float di = g_dinv[w];
    float4 v = t4[(size_t)w * 32 + lane];
    float cs = di * di;                      // self-loop norm
    float4 acc = make_float4(v.x * cs, v.y * cs, v.z * cs, v.w * cs);

    int j = g_rowptr[w], end = g_rowptr[w + 1];
    for (; j + 1 < end; j += 2) {
        int s0 = g_csr[j], s1 = g_csr[j + 1];
        float c0 = di * g_dinv[s0];
        float c1 = di * g_dinv[s1];
        float4 u0 = t4[(size_t)s0 * 32 + lane];
        float4 u1 = t4[(size_t)s1 * 32 + lane];
        acc.x = fmaf(u0.x, c0, fmaf(u1.x, c1, acc.x));
        acc.y = fmaf(u0.y, c0, fmaf(u1.y, c1, acc.y));
        acc.z = fmaf(u0.z, c0, fmaf(u1.z, c1, acc.z));
        acc.w = fmaf(u0.w, c0, fmaf(u1.w, c1, acc.w));
    }
    if (j < end) {
        int s0 = g_csr[j];
        float c0 = di * g_dinv[s0];
        float4 u0 = t4[(size_t)s0 * 32 + lane];
        acc.x = fmaf(u0.x, c0, acc.x);
        acc.y = fmaf(u0.y, c0, acc.y);
        acc.z = fmaf(u0.z, c0, acc.z);
        acc.w = fmaf(u0.w, c0, acc.w);
    }

    float4 b = ((const float4*)bias)[lane];
    acc.x += b.x; acc.y += b.y; acc.z += b.z; acc.w += b.w;

    if (act == 1) {            // relu
        acc.x = fmaxf(acc.x, 0.f); acc.y = fmaxf(acc.y, 0.f);
        acc.z = fmaxf(acc.z, 0.f); acc.w = fmaxf(acc.w, 0.f);
    } else if (act == 2) {     // sigmoid
        acc.x = 1.f / (1.f + __expf(-acc.x));
        acc.y = 1.f / (1.f + __expf(-acc.y));
        acc.z = 1.f / (1.f + __expf(-acc.z));
        acc.w = 1.f / (1.f + __expf(-acc.w));
    }
    ((float4*)out)[(size_t)w * 32 + lane] = acc;
}

// fused mu/logvar propagate + reparameterization z = eps*exp(0.5*lv) + mu
__global__ __launch_bounds__(256) void k_prop2(const float* __restrict__ tmu,
                                               const float* __restrict__ tlv,
                                               const float* __restrict__ bmu,
                                               const float* __restrict__ blv,
                                               const float* __restrict__ eps,
                                               float* __restrict__ omu,
                                               float* __restrict__ olv,
                                               float* __restrict__ oz, int n) {
    int w = (blockIdx.x * blockDim.x + threadIdx.x) >> 5;
    if (w >= n) return;
    int lane = threadIdx.x & 31;

    const float4* m4 = (const float4*)tmu;
    const float4* l4 = (const float4*)tlv;
    float di = g_dinv[w];
    float cs = di * di;
    float4 vm = m4[(size_t)w * 32 + lane];
    float4 vl = l4[(size_t)w * 32 + lane];
    float4 am = make_float4(vm.x * cs, vm.y * cs, vm.z * cs, vm.w * cs);
    float4 al = make_float4(vl.x * cs, vl.y * cs, vl.z * cs, vl.w * cs);

    int j = g_rowptr[w], end = g_rowptr[w + 1];
    for (; j < end; j++) {
        int s0 = g_csr[j];
        float c0 = di * g_dinv[s0];
        float4 um = m4[(size_t)s0 * 32 + lane];
        float4 ul = l4[(size_t)s0 * 32 + lane];
        am.x = fmaf(um.x, c0, am.x); am.y = fmaf(um.y, c0, am.y);
        am.z = fmaf(um.z, c0, am.z); am.w = fmaf(um.w, c0, am.w);
        al.x = fmaf(ul.x, c0, al.x); al.y = fmaf(ul.y, c0, al.y);
        al.z = fmaf(ul.z, c0, al.z); al.w = fmaf(ul.w, c0, al.w);
    }

    float4 b_m = ((const float4*)bmu)[lane];
    float4 b_l = ((const float4*)blv)[lane];
    am.x += b_m.x; am.y += b_m.y; am.z += b_m.z; am.w += b_m.w;
    al.x += b_l.x; al.y += b_l.y; al.z += b_l.z; al.w += b_l.w;

    ((float4*)omu)[(size_t)w * 32 + lane] = am;
    ((float4*)olv)[(size_t)w * 32 + lane] = al;

    float4 e = ((const float4*)eps)[(size_t)w * 32 + lane];
    float4 z;
    z.x = fmaf(e.x, __expf(0.5f * al.x), am.x);
    z.y = fmaf(e.y, __expf(0.5f * al.y), am.y);
    z.z = fmaf(e.z, __expf(0.5f * al.z), am.z);
    z.w = fmaf(e.w, __expf(0.5f * al.w), am.w);
    ((float4*)oz)[(size_t)w * 32 + lane] = z;
}

// ---------------- host ----------------
extern "C" void kernel_launch(void* const* d_in, const int* in_sizes, int n_in,
                              void* d_out, int out_size) {
    const float* x   = (const float*)d_in[0];
    const int*   ei  = (const int*)  d_in[1];
    const float* eps = (const float*)d_in[2];
    const float* W1  = (const float*)d_in[3];
    const float* b1  = (const float*)d_in[4];
    const float* Wmu = (const float*)d_in[5];
    const float* bmu = (const float*)d_in[6];
    const float* Wlv = (const float*)d_in[7];
    const float* blv = (const float*)d_in[8];

    int n = in_sizes[0] / F;
    int e = in_sizes[1] / 2;
    const int* src = ei;
    const int* dst = ei + e;

    float* out   = (float*)d_out;
    float* recon = out;
    float* omu   = out + (size_t)n * F;
    float* olv   = out + 2 * (size_t)n * F;

    void *p0, *p1, *ph, *pz;
    cudaGetSymbolAddress(&p0, g_buf0);
    cudaGetSymbolAddress(&p1, g_buf1);
    cudaGetSymbolAddress(&ph, g_h);
    cudaGetSymbolAddress(&pz, g_z);
    float* t0 = (float*)p0;
    float* t1 = (float*)p1;
    float* h  = (float*)ph;
    float* z  = (float*)pz;

    const int TB = 256;
    int gN = (n + TB - 1) / TB;
    int gE = (e + TB - 1) / TB;
    int gGemm = (n + 127) / 128;
    int gProp = ((size_t)n * 32 + TB - 1) / TB;

    // build CSR (by destination) + dinv
    k_zero_deg<<<gN, TB>>>(n);
    k_count<<<gE, TB>>>(dst, e);
    k_scan<<<1, 1024>>>(n);
    k_place<<<gE, TB>>>(src, dst, e);

    // conv1 + relu
    k_gemm<<<gGemm, TB>>>(x, W1, t0, n);
    k_prop<<<gProp, TB>>>(t0, b1, h, n, /*relu*/1);

    // conv_mu / conv_logvar (+ fused reparameterization)
    k_gemm<<<gGemm, TB>>>(h, Wmu, t0, n);
    k_gemm<<<gGemm, TB>>>(h, Wlv, t1, n);
    k_prop2<<<gProp, TB>>>(t0, t1, bmu, blv, eps, omu, olv, z, n);

    // decode: conv1(z) + sigmoid
    k_gemm<<<gGemm, TB>>>(z, W1, t0, n);
    k_prop<<<gProp, TB>>>(t0, b1, recon, n, /*sigmoid*/2);
}

// round 4
// speedup vs baseline: 1.6247x; 1.6247x over previous
#include <cuda_runtime.h>
#include <math.h>
#include <stdint.h>

#define F      128
#define NMAX   80000
#define EMAX   640000
#define SMS    132          // smem row stride (floats), conflict-free for frag loads

// ---------------- scratch (static device globals; no allocation) ----------------
__device__ __align__(16) float g_buf0[NMAX * F];   // prop output / GEMM input
__device__ __align__(16) float g_h   [NMAX * F];   // hidden after conv1+relu
__device__ __align__(16) float g_z   [NMAX * F];   // reparameterized latent
__device__ __align__(16) float g_wt1 [F * F];      // W1^T,  tf32-rounded
__device__ __align__(16) float g_wtmu[F * F];
__device__ __align__(16) float g_wtlv[F * F];
__device__ float g_dinv[NMAX];
__device__ float g_coef[EMAX];
__device__ int   g_deg [NMAX];
__device__ int   g_rowptr[NMAX + 1];
__device__ int   g_cur [NMAX];
__device__ int   g_csr [EMAX];
__device__ int   g_bsum[1024];

// ---------------- helpers ----------------
__device__ __forceinline__ float f2tf32(float x) {
    uint32_t b;
    asm("cvt.rna.tf32.f32 %0, %1;" : "=r"(b) : "f"(x));
    return __uint_as_float(b);
}
__device__ __forceinline__ void mma_tf32(float* c, const uint32_t* a, const uint32_t* b) {
    asm volatile(
        "mma.sync.aligned.m16n8k8.row.col.f32.tf32.tf32.f32 "
        "{%0,%1,%2,%3}, {%4,%5,%6,%7}, {%8,%9}, {%0,%1,%2,%3};"
        : "+f"(c[0]), "+f"(c[1]), "+f"(c[2]), "+f"(c[3])
        : "r"(a[0]), "r"(a[1]), "r"(a[2]), "r"(a[3]), "r"(b[0]), "r"(b[1]));
}

// ---------------- CSR construction (parallel scan) ----------------
__global__ void k_zero_deg(int n) {
    int i = blockIdx.x * blockDim.x + threadIdx.x;
    if (i < n) g_deg[i] = 0;
}
__global__ void k_count(const int* __restrict__ dst, int e) {
    int i = blockIdx.x * blockDim.x + threadIdx.x;
    if (i < e) atomicAdd(&g_deg[dst[i]], 1);
}
__global__ void k_scan1(int n) {
    __shared__ int s[256];
    int t = threadIdx.x;
    int i = blockIdx.x * 256 + t;
    int d = (i < n) ? g_deg[i] : 0;
    if (i < n) g_dinv[i] = rsqrtf((float)(d + 1));
    s[t] = d; __syncthreads();
#pragma unroll
    for (int off = 1; off < 256; off <<= 1) {
        int v = (t >= off) ? s[t - off] : 0;
        __syncthreads();
        s[t] += v;
        __syncthreads();
    }
    if (i < n) g_rowptr[i] = s[t] - d;
    if (t == 255) g_bsum[blockIdx.x] = s[255];
}
__global__ void k_scan2(int nb, int n) {
    __shared__ int s[512];
    int t = threadIdx.x;
    int v = (t < nb) ? g_bsum[t] : 0;
    s[t] = v; __syncthreads();
#pragma unroll
    for (int off = 1; off < 512; off <<= 1) {
        int u = (t >= off) ? s[t - off] : 0;
        __syncthreads();
        s[t] += u;
        __syncthreads();
    }
    if (t < nb) g_bsum[t] = s[t] - v;
    if (t == 511) g_rowptr[n] = s[511];
}
__global__ void k_scan3(int n) {
    int i = blockIdx.x * 256 + threadIdx.x;
    if (i < n) {
        int r = g_rowptr[i] + g_bsum[blockIdx.x];
        g_rowptr[i] = r;
        g_cur[i] = r;
    }
}
__global__ void k_place(const int* __restrict__ src, const int* __restrict__ dst, int e) {
    int i = blockIdx.x * blockDim.x + threadIdx.x;
    if (i < e) {
        int d = dst[i], s = src[i];
        int slot = atomicAdd(&g_cur[d], 1);
        g_csr[slot] = s;
        g_coef[slot] = g_dinv[s] * g_dinv[d];
    }
}

// ---------------- weight transpose + tf32 rounding ----------------
__global__ void k_prep_w(const float* __restrict__ W1, const float* __restrict__ Wmu,
                         const float* __restrict__ Wlv) {
    const float* src = (blockIdx.z == 0) ? W1 : (blockIdx.z == 1) ? Wmu : Wlv;
    float* dst = (blockIdx.z == 0) ? g_wt1 : (blockIdx.z == 1) ? g_wtmu : g_wtlv;
    __shared__ float t[32][33];
    int tx = threadIdx.x, ty = threadIdx.y;
    int bx = blockIdx.x * 32, by = blockIdx.y * 32;
#pragma unroll
    for (int i = 0; i < 32; i += 8)
        t[ty + i][tx] = src[(by + ty + i) * F + bx + tx];
    __syncthreads();
#pragma unroll
    for (int i = 0; i < 32; i += 8)
        dst[(bx + ty + i) * F + by + tx] = f2tf32(t[tx][ty + i]);
}

// ---------------- propagation: out = D^-1/2 (A+I) D^-1/2 t  (no bias/act) ----------------
// one warp per destination node; lane handles 4 features (float4). Pure gather.
__global__ __launch_bounds__(256) void k_prop(const float* __restrict__ t,
                                              float* __restrict__ out, int n) {
    int w = (blockIdx.x * blockDim.x + threadIdx.x) >> 5;
    if (w >= n) return;
    int lane = threadIdx.x & 31;

    const float4* t4 = (const float4*)t;
    float di = g_dinv[w];
    float4 v = t4[(size_t)w * 32 + lane];
    float cs = di * di;
    float4 acc = make_float4(v.x * cs, v.y * cs, v.z * cs, v.w * cs);

    int j = g_rowptr[w], end = g_rowptr[w + 1];
    for (; j + 1 < end; j += 2) {
        int s0 = g_csr[j], s1 = g_csr[j + 1];
        float c0 = g_coef[j], c1 = g_coef[j + 1];
        float4 u0 = t4[(size_t)s0 * 32 + lane];
        float4 u1 = t4[(size_t)s1 * 32 + lane];
        acc.x = fmaf(u0.x, c0, fmaf(u1.x, c1, acc.x));
        acc.y = fmaf(u0.y, c0, fmaf(u1.y, c1, acc.y));
        acc.z = fmaf(u0.z, c0, fmaf(u1.z, c1, acc.z));
        acc.w = fmaf(u0.w, c0, fmaf(u1.w, c1, acc.w));
    }
    if (j < end) {
        int s0 = g_csr[j];
        float c0 = g_coef[j];
        float4 u0 = t4[(size_t)s0 * 32 + lane];
        acc.x = fmaf(u0.x, c0, acc.x);
        acc.y = fmaf(u0.y, c0, acc.y);
        acc.z = fmaf(u0.z, c0, acc.z);
        acc.w = fmaf(u0.w, c0, acc.w);
    }
    ((float4*)out)[(size_t)w * 32 + lane] = acc;
}

// ---------------- TF32 mma.sync GEMM: C[n x 128] = A[n x 128] @ Bt^T + bias, + epilogue ----
// Bt: [128 out][128 k] row-major, pre-transposed & tf32-rounded.
// mode 1: C0 = relu(A Wt0^T + bias0)
// mode 2: C0 = sigmoid(A Wt0^T + bias0)
// mode 3: C0 = A Wt0^T + bias0 (mu); C1 = A Wt1^T + bias1 (logvar);
//         Cz = eps * exp(0.5*lv) + mu
__global__ __launch_bounds__(256, 1) void k_gemm_mma(
    const float* __restrict__ A,
    const float* __restrict__ Bt0, const float* __restrict__ Bt1,
    const float* __restrict__ bias0, const float* __restrict__ bias1,
    const float* __restrict__ eps,
    float* __restrict__ C0, float* __restrict__ C1, float* __restrict__ Cz,
    int n, int mode)
{
    extern __shared__ float smf[];
    float* As  = smf;                 // 128 x SMS
    float* Bs0 = As + 128 * SMS;
    float* Bs1 = Bs0 + 128 * SMS;     // only mode 3

    const int tid = threadIdx.x;
    const int row0 = blockIdx.x * 128;
    const int nbt = (mode == 3) ? 2 : 1;

    // stage A (tf32-round on the fly): 4096 float4 loads
    for (int t = tid; t < 4096; t += 256) {
        int r = t >> 5, q = t & 31;
        int gr = row0 + r; if (gr >= n) gr = n - 1;
        float4 v = *(const float4*)(A + (size_t)gr * F + q * 4);
        v.x = f2tf32(v.x); v.y = f2tf32(v.y); v.z = f2tf32(v.z); v.w = f2tf32(v.w);
        *(float4*)(As + r * SMS + q * 4) = v;
    }
    // stage B tile(s) (already tf32)
    for (int bt = 0; bt < nbt; bt++) {
        const float* Bt = bt ? Bt1 : Bt0;
        float* Bs = bt ? Bs1 : Bs0;
        for (int t = tid; t < 4096; t += 256) {
            int r = t >> 5, q = t & 31;
            float4 v = *(const float4*)(Bt + (size_t)r * F + q * 4);
            *(float4*)(Bs + r * SMS + q * 4) = v;
        }
    }
    __syncthreads();

    const int warp = tid >> 5, lane = tid & 31;
    const int wm = warp & 3;          // m-band: 4 x 32 rows
    const int wn = warp >> 2;         // n-band: 2 x 64 cols
    const int gid = lane >> 2, tig = lane & 3;

    const float* Aw = As + (wm * 32) * SMS;

    for (int bt = 0; bt < nbt; bt++) {
        const float* Bs = bt ? Bs1 : Bs0;
        const float* Bw = Bs + (wn * 64) * SMS;

        float c[2][8][4];
#pragma unroll
        for (int i = 0; i < 2; i++)
#pragma unroll
            for (int j = 0; j < 8; j++)
#pragma unroll
                for (int q = 0; q < 4; q++) c[i][j][q] = 0.0f;

        for (int kk = 0; kk < F; kk += 8) {
            uint32_t a[2][4], b[8][2];
#pragma unroll
            for (int i = 0; i < 2; i++) {
                const float* ap = Aw + (i * 16 + gid) * SMS + kk + tig;
                a[i][0] = __float_as_uint(ap[0]);
                a[i][1] = __float_as_uint(ap[8 * SMS]);
                a[i][2] = __float_as_uint(ap[4]);
                a[i][3] = __float_as_uint(ap[8 * SMS + 4]);
            }
#pragma unroll
            for (int j = 0; j < 8; j++) {
                const float* bp = Bw + (j * 8 + gid) * SMS + kk + tig;
                b[j][0] = __float_as_uint(bp[0]);
                b[j][1] = __float_as_uint(bp[4]);
            }
#pragma unroll
            for (int i = 0; i < 2; i++)
#pragma unroll
                for (int j = 0; j < 8; j++)
                    mma_tf32(c[i][j], a[i], b[j]);
        }

        // epilogue
        const float* bias = bt ? bias1 : bias0;
        float* C = bt ? C1 : C0;
#pragma unroll
        for (int i = 0; i < 2; i++) {
            int r0 = row0 + wm * 32 + i * 16 + gid;
            int r1 = r0 + 8;
#pragma unroll
            for (int j = 0; j < 8; j++) {
                int col = wn * 64 + j * 8 + tig * 2;
                float bx = bias[col], by = bias[col + 1];
                float v00 = c[i][j][0] + bx, v01 = c[i][j][1] + by;
                float v10 = c[i][j][2] + bx, v11 = c[i][j][3] + by;
                if (mode == 1) {
                    v00 = fmaxf(v00, 0.f); v01 = fmaxf(v01, 0.f);
                    v10 = fmaxf(v10, 0.f); v11 = fmaxf(v11, 0.f);
                } else if (mode == 2) {
                    v00 = 1.f / (1.f + __expf(-v00)); v01 = 1.f / (1.f + __expf(-v01));
                    v10 = 1.f / (1.f + __expf(-v10)); v11 = 1.f / (1.f + __expf(-v11));
                }
                if (r0 < n) *(float2*)(C + (size_t)r0 * F + col) = make_float2(v00, v01);
                if (r1 < n) *(float2*)(C + (size_t)r1 * F + col) = make_float2(v10, v11);

                if (mode == 3 && bt == 1) {
                    // v = logvar just stored; mu was stored by THIS thread in bt=0
                    if (r0 < n) {
                        float2 mu = *(const float2*)(C0 + (size_t)r0 * F + col);
                        float2 ev = *(const float2*)(eps + (size_t)r0 * F + col);
                        float2 z;
                        z.x = fmaf(ev.x, __expf(0.5f * v00), mu.x);
                        z.y = fmaf(ev.y, __expf(0.5f * v01), mu.y);
                        *(float2*)(Cz + (size_t)r0 * F + col) = z;
                    }
                    if (r1 < n) {
                        float2 mu = *(const float2*)(C0 + (size_t)r1 * F + col);
                        float2 ev = *(const float2*)(eps + (size_t)r1 * F + col);
                        float2 z;
                        z.x = fmaf(ev.x, __expf(0.5f * v10), mu.x);
                        z.y = fmaf(ev.y, __expf(0.5f * v11), mu.y);
                        *(float2*)(Cz + (size_t)r1 * F + col) = z;
                    }
                }
            }
        }
    }
}

// ---------------- host ----------------
extern "C" void kernel_launch(void* const* d_in, const int* in_sizes, int n_in,
                              void* d_out, int out_size) {
    const float* x   = (const float*)d_in[0];
    const int*   ei  = (const int*)  d_in[1];
    const float* eps = (const float*)d_in[2];
    const float* W1  = (const float*)d_in[3];
    const float* b1  = (const float*)d_in[4];
    const float* Wmu = (const float*)d_in[5];
    const float* bmu = (const float*)d_in[6];
    const float* Wlv = (const float*)d_in[7];
    const float* blv = (const float*)d_in[8];

    int n = in_sizes[0] / F;
    int e = in_sizes[1] / 2;
    const int* src = ei;
    const int* dst = ei + e;

    float* out   = (float*)d_out;
    float* recon = out;
    float* omu   = out + (size_t)n * F;
    float* olv   = out + 2 * (size_t)n * F;

    void *p0, *ph, *pz, *pw1, *pwmu, *pwlv;
    cudaGetSymbolAddress(&p0, g_buf0);
    cudaGetSymbolAddress(&ph, g_h);
    cudaGetSymbolAddress(&pz, g_z);
    cudaGetSymbolAddress(&pw1, g_wt1);
    cudaGetSymbolAddress(&pwmu, g_wtmu);
    cudaGetSymbolAddress(&pwlv, g_wtlv);
    float* t0   = (float*)p0;
    float* h    = (float*)ph;
    float* z    = (float*)pz;
    float* wt1  = (float*)pw1;
    float* wtmu = (float*)pwmu;
    float* wtlv = (float*)pwlv;

    const int TB = 256;
    int gN = (n + TB - 1) / TB;
    int gE = (e + TB - 1) / TB;
    int gScan = (n + 255) / 256;
    int gGemm = (n + 127) / 128;
    int gProp = (int)(((size_t)n * 32 + TB - 1) / TB);

    size_t smem1 = 2 * 128 * SMS * sizeof(float);   // A + 1 B tile
    size_t smem2 = 3 * 128 * SMS * sizeof(float);   // A + 2 B tiles
    cudaFuncSetAttribute(k_gemm_mma, cudaFuncAttributeMaxDynamicSharedMemorySize,
                         (int)smem2);

    // CSR + dinv + per-edge coefficients
    k_zero_deg<<<gN, TB>>>(n);
    k_count<<<gE, TB>>>(dst, e);
    k_scan1<<<gScan, 256>>>(n);
    k_scan2<<<1, 512>>>(gScan, n);
    k_scan3<<<gScan, 256>>>(n);
    k_place<<<gE, TB>>>(src, dst, e);

    // weights: transpose + tf32 rounding
    k_prep_w<<<dim3(4, 4, 3), dim3(32, 8)>>>(W1, Wmu, Wlv);

    // encode: h = relu((P x) W1 + b1)
    k_prop<<<gProp, TB>>>(x, t0, n);
    k_gemm_mma<<<gGemm, 256, smem1>>>(t0, wt1, nullptr, b1, nullptr, nullptr,
                                      h, nullptr, nullptr, n, 1);

    // mu/logvar: shared prop of h, fused dual GEMM + reparameterization
    k_prop<<<gProp, TB>>>(h, t0, n);
    k_gemm_mma<<<gGemm, 256, smem2>>>(t0, wtmu, wtlv, bmu, blv, eps,
                                      omu, olv, z, n, 3);

    // decode: recon = sigmoid((P z) W1 + b1)
    k_prop<<<gProp, TB>>>(z, t0, n);
    k_gemm_mma<<<gGemm, 256, smem1>>>(t0, wt1, nullptr, b1, nullptr, nullptr,
                                      recon, nullptr, nullptr, n, 2);
}